// round 10
// baseline (speedup 1.0000x reference)
#include <cuda_runtime.h>
#include <cuda_bf16.h>
#include <cstdint>
#include <math.h>

#define D      4096
#define E      512
#define BROWS  8192
#define NQ     (1ull*BROWS*D)
#define NENC   (1ull*BROWS*E)

#define OUT_Q_OFF    1ull
#define OUT_PERP_OFF (1ull + NQ)
#define OUT_ENC_OFF  (2ull + NQ)

#define MARGIN 32.0f
#define CAP    16

// ---------------- device scratch ----------------
__device__ float              g_cnorm[E];
__device__ uint8_t            g_C8[(size_t)E * D];        // 2 MB e4m3 codebook
__device__ unsigned long long g_best[BROWS];              // packed (dist,idx) min
__device__ unsigned long long g_cand[(size_t)BROWS * CAP];
__device__ int                g_ccnt[BROWS];
__device__ int                g_counts[E];
__device__ double             g_loss;

#define SWZ128(off) ((off) ^ (((off) >> 3) & 0x70))

__device__ __forceinline__ uint32_t smem_to_u32(const void* p) {
    uint32_t a;
    asm("{ .reg .u64 t; cvta.to.shared.u64 t, %1; cvt.u32.u64 %0, t; }" : "=r"(a) : "l"(p));
    return a;
}

// float4 -> 4 packed e4m3 bytes (memory order x,y,z,w)
__device__ __forceinline__ uint32_t f4_to_e4m3(float4 v) {
    uint16_t lo, hi;
    asm("cvt.rn.satfinite.e4m3x2.f32 %0, %1, %2;" : "=h"(lo) : "f"(v.y), "f"(v.x));
    asm("cvt.rn.satfinite.e4m3x2.f32 %0, %1, %2;" : "=h"(hi) : "f"(v.w), "f"(v.z));
    return (uint32_t)lo | ((uint32_t)hi << 16);
}

// key packing: monotone float -> u32, argmin with ties -> lowest index
__device__ __forceinline__ unsigned long long make_key(float d, int idx) {
    unsigned int u = __float_as_uint(d);
    u = (u & 0x80000000u) ? ~u : (u | 0x80000000u);
    return ((unsigned long long)u << 32) | (unsigned int)idx;
}
__device__ __forceinline__ float key_to_float(unsigned long long k) {
    unsigned int u = (unsigned int)(k >> 32);
    u = (u & 0x80000000u) ? (u ^ 0x80000000u) : ~u;
    return __uint_as_float(u);
}

// ---------------- init ----------------
__global__ void init_kernel() {
    int i = blockIdx.x * blockDim.x + threadIdx.x;
    if (i < BROWS) { g_best[i] = 0xFFFFFFFFFFFFFFFFull; g_ccnt[i] = 0; }
    if (i < E)     g_counts[i] = 0;
    if (i == 0)    g_loss = 0.0;
}

// ---------------- codebook: e4m3 convert + exact norms (fused, 1 read) ----------------
__global__ __launch_bounds__(128)
void convCnorm_kernel(const float* __restrict__ C) {
    const int e = blockIdx.x;
    const float4* row = (const float4*)(C + (size_t)e * D);
    uint4* brow = (uint4*)(g_C8 + (size_t)e * D);
    float s = 0.f;
#pragma unroll
    for (int j = threadIdx.x; j < D / 16; j += 128) {
        float4 v0 = row[j * 4 + 0], v1 = row[j * 4 + 1];
        float4 v2 = row[j * 4 + 2], v3 = row[j * 4 + 3];
        uint4 p;
        p.x = f4_to_e4m3(v0); p.y = f4_to_e4m3(v1);
        p.z = f4_to_e4m3(v2); p.w = f4_to_e4m3(v3);
        brow[j] = p;
        s += v0.x*v0.x + v0.y*v0.y + v0.z*v0.z + v0.w*v0.w;
        s += v1.x*v1.x + v1.y*v1.y + v1.z*v1.z + v1.w*v1.w;
        s += v2.x*v2.x + v2.y*v2.y + v2.z*v2.z + v2.w*v2.w;
        s += v3.x*v3.x + v3.y*v3.y + v3.z*v3.z + v3.w*v3.w;
    }
    for (int o = 16; o; o >>= 1) s += __shfl_down_sync(0xffffffffu, s, o);
    __shared__ float ws[4];
    if ((threadIdx.x & 31) == 0) ws[threadIdx.x >> 5] = s;
    __syncthreads();
    if (threadIdx.x == 0) g_cnorm[e] = ws[0] + ws[1] + ws[2] + ws[3];
}

// ---------------- mma.sync e4m3 GEMM + fused argmin/candidates ----------------
// CTA 256 thr = 8 warps (2M x 4N), tile M=128 x N=256, warp tile 64x64.
// K chunk = 128 e4m3 elements (128B SW128 rows), double-buffered smem.
#define TM 128
#define TN 256
#define CH 128
#define NCHUNK (D / CH)          // 32
#define A_BYTES 16384            // 128 rows * 128B
#define B_BYTES 32768            // 256 rows * 128B
#define GEMM_SMEM (2*A_BYTES + 2*B_BYTES)   // 98304

__global__ __launch_bounds__(256, 1)
void gemm_mma_kernel(const float* __restrict__ X) {
    extern __shared__ __align__(1024) char smem[];
    const int tid  = threadIdx.x;
    const int lane = tid & 31;
    const int wid  = tid >> 5;
    const int warpM = wid >> 2;   // 0..1
    const int warpN = wid & 3;    // 0..3
    const int rowBase = blockIdx.y * TM;
    const int colBase = blockIdx.x * TN;

    uint32_t sbA[2] = { smem_to_u32(smem),             smem_to_u32(smem) + A_BYTES };
    uint32_t sbB[2] = { smem_to_u32(smem) + 2*A_BYTES, smem_to_u32(smem) + 2*A_BYTES + B_BYTES };
    char* pA[2] = { smem, smem + A_BYTES };

    const float* Xg0 = X + (size_t)rowBase * D;
    const uint8_t* Cg0 = g_C8 + (size_t)colBase * D;

    // A: 2 thr/row, each covers 64B (16 e4m3-u32 from 16 float4)
    const int ar = tid >> 1, ahalf = tid & 1;    // row 0..127, half 0/1
    // B: 8 thr/row (16B each), rows br + i*32
    const int br = tid >> 3, bc16 = tid & 7;

    float acc[4][8][4];
#pragma unroll
    for (int mi = 0; mi < 4; mi++)
#pragma unroll
        for (int ni = 0; ni < 8; ni++)
#pragma unroll
            for (int r = 0; r < 4; r++) acc[mi][ni][r] = 0.f;

    uint32_t av[16];   // converted A chunk: 16 x 4 e4m3 bytes = 64B

    // ---- preload chunk 0 ----
#pragma unroll
    for (int i = 0; i < 8; i++) {
        int r = br + i * 32;
        uint32_t dst = sbB[0] + SWZ128((uint32_t)(r * 128 + bc16 * 16));
        const uint8_t* src = Cg0 + (size_t)r * D + bc16 * 16;
        asm volatile("cp.async.cg.shared.global [%0], [%1], 16;" :: "r"(dst), "l"(src));
    }
    asm volatile("cp.async.commit_group;" ::: "memory");
    {
        const float* asrc = Xg0 + (size_t)ar * D + ahalf * 64;
#pragma unroll
        for (int i = 0; i < 16; i++)
            av[i] = f4_to_e4m3(*(const float4*)(asrc + i * 4));
    }

    const int a_r = lane & 15;
    const int a_c = (lane >> 4) * 16;
    const int b_n = ((lane >> 4) << 3) + (lane & 7);
    const int b_c = ((lane >> 3) & 1) * 16;

    for (int kt = 0; kt < NCHUNK; kt++) {
        const int buf = kt & 1;

        // STS A chunk kt (4 x uint4, SW128)
#pragma unroll
        for (int i4 = 0; i4 < 4; i4++) {
            uint4 p = make_uint4(av[i4*4+0], av[i4*4+1], av[i4*4+2], av[i4*4+3]);
            uint32_t off = SWZ128((uint32_t)(ar * 128 + ahalf * 64 + i4 * 16));
            *(uint4*)(pA[buf] + off) = p;
        }
        asm volatile("cp.async.wait_group 0;" ::: "memory");
        __syncthreads();

        // prefetch next chunk (overlaps MMA below)
        if (kt + 1 < NCHUNK) {
            const int nb = buf ^ 1;
            const int k0 = (kt + 1) * CH;
#pragma unroll
            for (int i = 0; i < 8; i++) {
                int r = br + i * 32;
                uint32_t dst = sbB[nb] + SWZ128((uint32_t)(r * 128 + bc16 * 16));
                const uint8_t* src = Cg0 + (size_t)r * D + k0 + bc16 * 16;
                asm volatile("cp.async.cg.shared.global [%0], [%1], 16;" :: "r"(dst), "l"(src));
            }
            asm volatile("cp.async.commit_group;" ::: "memory");
            const float* asrc = Xg0 + (size_t)ar * D + k0 + ahalf * 64;
#pragma unroll
            for (int i = 0; i < 16; i++)
                av[i] = f4_to_e4m3(*(const float4*)(asrc + i * 4));
        }

        // ---- compute: 4 k32 steps ----
        const uint32_t aB = sbA[buf], bB = sbB[buf];
#pragma unroll
        for (int kk = 0; kk < 4; kk++) {
            uint32_t af[4][4], bfr[4][4];
#pragma unroll
            for (int mi = 0; mi < 4; mi++) {
                uint32_t addr = aB + SWZ128((uint32_t)((warpM * 64 + mi * 16 + a_r) * 128 + kk * 32 + a_c));
                asm volatile("ldmatrix.sync.aligned.m8n8.x4.shared.b16 {%0,%1,%2,%3}, [%4];"
                    : "=r"(af[mi][0]), "=r"(af[mi][1]), "=r"(af[mi][2]), "=r"(af[mi][3]) : "r"(addr));
            }
#pragma unroll
            for (int ng = 0; ng < 4; ng++) {
                uint32_t addr = bB + SWZ128((uint32_t)((warpN * 64 + ng * 16 + b_n) * 128 + kk * 32 + b_c));
                asm volatile("ldmatrix.sync.aligned.m8n8.x4.shared.b16 {%0,%1,%2,%3}, [%4];"
                    : "=r"(bfr[ng][0]), "=r"(bfr[ng][1]), "=r"(bfr[ng][2]), "=r"(bfr[ng][3]) : "r"(addr));
            }
#pragma unroll
            for (int mi = 0; mi < 4; mi++)
#pragma unroll
                for (int ng = 0; ng < 4; ng++) {
                    asm volatile("mma.sync.aligned.m16n8k32.row.col.f32.e4m3.e4m3.f32 "
                        "{%0,%1,%2,%3}, {%4,%5,%6,%7}, {%8,%9}, {%0,%1,%2,%3};"
                        : "+f"(acc[mi][2*ng][0]), "+f"(acc[mi][2*ng][1]),
                          "+f"(acc[mi][2*ng][2]), "+f"(acc[mi][2*ng][3])
                        : "r"(af[mi][0]), "r"(af[mi][1]), "r"(af[mi][2]), "r"(af[mi][3]),
                          "r"(bfr[ng][0]), "r"(bfr[ng][1]));
                    asm volatile("mma.sync.aligned.m16n8k32.row.col.f32.e4m3.e4m3.f32 "
                        "{%0,%1,%2,%3}, {%4,%5,%6,%7}, {%8,%9}, {%0,%1,%2,%3};"
                        : "+f"(acc[mi][2*ng+1][0]), "+f"(acc[mi][2*ng+1][1]),
                          "+f"(acc[mi][2*ng+1][2]), "+f"(acc[mi][2*ng+1][3])
                        : "r"(af[mi][0]), "r"(af[mi][1]), "r"(af[mi][2]), "r"(af[mi][3]),
                          "r"(bfr[ng][2]), "r"(bfr[ng][3]));
                }
        }
    }

    // ---- fused epilogue: per-CTA row argmin + candidate push ----
    __shared__ unsigned long long rowbest[TM];
    for (int i = tid; i < TM; i += 256) rowbest[i] = 0xFFFFFFFFFFFFFFFFull;
    __syncthreads();

    const int g = lane >> 2, t = lane & 3;
#pragma unroll
    for (int mi = 0; mi < 4; mi++) {
#pragma unroll
        for (int rr = 0; rr < 2; rr++) {
            int lrow = warpM * 64 + mi * 16 + rr * 8 + g;
            unsigned long long best = 0xFFFFFFFFFFFFFFFFull;
#pragma unroll
            for (int ni = 0; ni < 8; ni++) {
                int col = colBase + warpN * 64 + ni * 8 + 2 * t;
                float d0 = g_cnorm[col]     - 2.f * acc[mi][ni][rr * 2 + 0];
                float d1 = g_cnorm[col + 1] - 2.f * acc[mi][ni][rr * 2 + 1];
                unsigned long long k0 = make_key(d0, col);
                unsigned long long k1 = make_key(d1, col + 1);
                if (k0 < best) best = k0;
                if (k1 < best) best = k1;
            }
            atomicMin(&rowbest[lrow], best);
        }
    }
    __syncthreads();
    for (int i = tid; i < TM; i += 256)
        atomicMin(&g_best[rowBase + i], rowbest[i]);

#pragma unroll
    for (int mi = 0; mi < 4; mi++) {
#pragma unroll
        for (int rr = 0; rr < 2; rr++) {
            int lrow = warpM * 64 + mi * 16 + rr * 8 + g;
            int grow = rowBase + lrow;
            float thr = key_to_float(rowbest[lrow]) + MARGIN;
#pragma unroll
            for (int ni = 0; ni < 8; ni++) {
                int col = colBase + warpN * 64 + ni * 8 + 2 * t;
                float d0 = g_cnorm[col]     - 2.f * acc[mi][ni][rr * 2 + 0];
                float d1 = g_cnorm[col + 1] - 2.f * acc[mi][ni][rr * 2 + 1];
                if (d0 <= thr) {
                    int p = atomicAdd(&g_ccnt[grow], 1);
                    if (p < CAP) g_cand[(size_t)grow * CAP + p] = make_key(d0, col);
                }
                if (d1 <= thr) {
                    int p = atomicAdd(&g_ccnt[grow], 1);
                    if (p < CAP) g_cand[(size_t)grow * CAP + p] = make_key(d1, col + 1);
                }
            }
        }
    }
}

// ---------------- fused rescue + finalize ----------------
__global__ __launch_bounds__(256)
void epilogue_kernel(const float* __restrict__ X,
                     const float* __restrict__ C,
                     float* __restrict__ out) {
    __shared__ float q[D];
    __shared__ float ws[8];
    __shared__ int   cand[E];
    __shared__ int   ncand;
    __shared__ float xnorm_s;
    __shared__ int   s_idx;

    const int row = blockIdx.x;
    const int tid = threadIdx.x;
    const int lane = tid & 31, wid = tid >> 5;

    const unsigned long long bk = g_best[row];
    const float gd = key_to_float(bk);
    const int gidx = (int)(bk & 0xffffffffull);
    const int cnt = g_ccnt[row];

    if (tid == 0) ncand = 0;
    __syncthreads();
    if (cnt > CAP) {
        // overflow: exact rescue over all codes
        for (int i = tid; i < E; i += 256) cand[i] = i;
        if (tid == 0) ncand = E;
    } else {
        if (tid < cnt) {
            unsigned long long k = g_cand[(size_t)row * CAP + tid];
            if (key_to_float(k) <= gd + MARGIN) {
                int p = atomicAdd(&ncand, 1);
                cand[p] = (int)(k & 0xffffffffull);
            }
        }
    }
    __syncthreads();
    int n = ncand;
    const float4* x4 = (const float4*)(X + (size_t)row * D);

    if (n <= 1) {
        if (tid == 0) s_idx = gidx;
        __syncthreads();
    } else {
        float xs = 0.f;
#pragma unroll
        for (int i = tid; i < D / 4; i += 256) {
            float4 xv = x4[i];
            xs += xv.x * xv.x + xv.y * xv.y + xv.z * xv.z + xv.w * xv.w;
        }
        for (int o = 16; o; o >>= 1) xs += __shfl_down_sync(0xffffffffu, xs, o);
        if (lane == 0) ws[wid] = xs;
        __syncthreads();
        if (tid == 0) {
            float t = 0.f;
#pragma unroll
            for (int w = 0; w < 8; w++) t += ws[w];
            xnorm_s = t;
        }
        unsigned long long bestE = 0xFFFFFFFFFFFFFFFFull;
        for (int t = 0; t < n; t++) {
            int cidx = cand[t];
            const float4* c4 = (const float4*)(C + (size_t)cidx * D);
            float s = 0.f;
#pragma unroll
            for (int i = tid; i < D / 4; i += 256) {
                float4 xv = x4[i];
                float4 cv = c4[i];
                s += xv.x * cv.x + xv.y * cv.y + xv.z * cv.z + xv.w * cv.w;
            }
            for (int o = 16; o; o >>= 1) s += __shfl_down_sync(0xffffffffu, s, o);
            __syncthreads();
            if (lane == 0) ws[wid] = s;
            __syncthreads();
            if (tid == 0) {
                float dot = 0.f;
#pragma unroll
                for (int w = 0; w < 8; w++) dot += ws[w];
                float dist = (xnorm_s + g_cnorm[cidx]) - 2.f * dot;
                unsigned long long kk = make_key(dist, cidx);
                bestE = (kk < bestE) ? kk : bestE;
            }
        }
        if (tid == 0) s_idx = (int)(bestE & 0xffffffffull);
        __syncthreads();
    }

    const int idx = s_idx;

    // ---- finalize ----
    const float4* c4 = (const float4*)(C + (size_t)idx * D);
    float s = 0.f;
#pragma unroll
    for (int i = tid; i < D / 4; i += 256) {
        float4 xv = x4[i];
        float4 cv = c4[i];
        float d0 = cv.x - xv.x, d1 = cv.y - xv.y, d2 = cv.z - xv.z, d3 = cv.w - xv.w;
        q[i * 4 + 0] = xv.x + d0;
        q[i * 4 + 1] = xv.y + d1;
        q[i * 4 + 2] = xv.z + d2;
        q[i * 4 + 3] = xv.w + d3;
        s += d0 * d0 + d1 * d1 + d2 * d2 + d3 * d3;
    }
    for (int o = 16; o; o >>= 1) s += __shfl_down_sync(0xffffffffu, s, o);
    if (lane == 0) ws[wid] = s;
    __syncthreads();
    if (tid == 0) {
        float t = 0.f;
#pragma unroll
        for (int w = 0; w < 8; w++) t += ws[w];
        atomicAdd(&g_loss, (double)t);
        atomicAdd(&g_counts[idx], 1);
    }

    float* qo = out + OUT_Q_OFF + (size_t)row * D;
    if (tid == 0) { qo[0] = q[0]; qo[1] = q[1]; qo[2] = q[2]; qo[D - 1] = q[D - 1]; }
#pragma unroll
    for (int i = tid; i < 1023; i += 256) {
        int kq = 3 + i * 4;
        *(float4*)(qo + kq) = make_float4(q[kq], q[kq + 1], q[kq + 2], q[kq + 3]);
    }

    float* enc = out + OUT_ENC_OFF + (size_t)row * E;
    if (tid == 0) {
        enc[0]   = (idx == 0)   ? 1.f : 0.f;
        enc[1]   = (idx == 1)   ? 1.f : 0.f;
        enc[510] = (idx == 510) ? 1.f : 0.f;
        enc[511] = (idx == 511) ? 1.f : 0.f;
    }
    for (int i = tid; i < 127; i += 256) {
        int kq = 2 + i * 4;
        float4 v = make_float4((idx == kq) ? 1.f : 0.f, (idx == kq + 1) ? 1.f : 0.f,
                               (idx == kq + 2) ? 1.f : 0.f, (idx == kq + 3) ? 1.f : 0.f);
        *(float4*)(enc + kq) = v;
    }
}

// ---------------- scalars ----------------
__global__ void scalars_kernel(float* __restrict__ out) {
    const int e = threadIdx.x;  // 512 threads
    float p = (float)g_counts[e] / (float)BROWS;
    float term = p * logf(p + 1e-10f);
    for (int o = 16; o; o >>= 1) term += __shfl_down_sync(0xffffffffu, term, o);
    __shared__ float ws[16];
    if ((e & 31) == 0) ws[e >> 5] = term;
    __syncthreads();
    if (e == 0) {
        float H = 0.f;
        for (int w = 0; w < 16; w++) H += ws[w];
        out[0] = (float)(1.25 * (g_loss / (double)NQ));
        out[OUT_PERP_OFF] = expf(-H);
    }
}

// ---------------- launch ----------------
extern "C" void kernel_launch(void* const* d_in, const int* in_sizes, int n_in,
                              void* d_out, int out_size) {
    const float* X = (const float*)d_in[0];
    const float* C = (const float*)d_in[1];
    if (n_in >= 2 && in_sizes[0] == E * D && in_sizes[1] == BROWS * D) {
        const float* t = X; X = C; C = t;
    }
    float* out = (float*)d_out;

    static bool attr_done = false;
    if (!attr_done) {
        cudaFuncSetAttribute(gemm_mma_kernel,
                             cudaFuncAttributeMaxDynamicSharedMemorySize, GEMM_SMEM);
        attr_done = true;
    }

    init_kernel<<<BROWS / 256, 256>>>();
    convCnorm_kernel<<<E, 128>>>(C);
    dim3 grid(E / TN, BROWS / TM);   // (2, 64)
    gemm_mma_kernel<<<grid, 256, GEMM_SMEM>>>(X);
    epilogue_kernel<<<BROWS, 256>>>(X, C, out);
    scalars_kernel<<<1, E>>>(out);
}